// round 17
// baseline (speedup 1.0000x reference)
#include <cuda_runtime.h>
#include <cuda_bf16.h>
#include <math.h>
#include <stdint.h>

// STAttn fused, GB300 sm_103a. Round 17 (= round 15 resubmit x2; broker
// timeouts):
//  - prep kernel deleted (weights split inline, per chunk)
//  - fast truncation hi/lo split (PRMT + cvt.bf16x2): ~2.5x fewer ALU ops
//  - single-buffered x and W (phase barriers already serialize) -> 70.7KB smem
//    -> 3 CTAs/SM on main
//  - fc re-tiled to 128 CTAs (32bt x 64out), inline fc1_w split
// B=32,T=32 (BT=1024), N=64, D=512, H=64, OUT=256.

#define NB 64
#define DD 512
#define HH 64
#define OUTC 256
#define BT 1024
#define KCHUNK 128

// ---- main smem (bf16 units) ----
#define PCH 136                      // chunk pitch (128+8) -> conflict-free
#define PLANE_BF (64 * PCH)          // 8704 bf16: one 64x128 plane
#define WB_OFF (2 * PLANE_BF)        // x (hi|lo) then W (hi|lo)
#define MISC_BF (4 * PLANE_BF)       // 34816 bf16
#define SMEM_MAIN_BYTES (MISC_BF * 2 + 256 * 4)   // 70656 B -> 3 CTAs/SM

// ---- fc smem (bf16 units) ----
#define FA_PLANE (32 * PCH)          // 4352
#define FW_OFF (2 * FA_PLANE)        // A (hi|lo) then W (hi|lo)
#define FW_PLANE (64 * PCH)          // 8704
#define FMISC (FW_OFF + 2 * FW_PLANE)
#define SMEMF_BYTES (FMISC * 2)      // 52224 B

__device__ __align__(16) __nv_bfloat16 g_attr_h[BT * DD];
__device__ __align__(16) __nv_bfloat16 g_attr_l[BT * DD];

// ---------------- helpers ----------------
__device__ __forceinline__ uint32_t ld_u32(const void* p) {
    return *reinterpret_cast<const uint32_t*>(p);
}
__device__ __forceinline__ void cp_async16(uint32_t s, const void* g) {
    asm volatile("cp.async.cg.shared.global [%0], [%1], 16;\n" :: "r"(s), "l"(g));
}
__device__ __forceinline__ void cp_commit() { asm volatile("cp.async.commit_group;\n"); }
template <int N> __device__ __forceinline__ void cp_wait() {
    asm volatile("cp.async.wait_group %0;\n" :: "n"(N));
}
__device__ __forceinline__ uint32_t smem_u32(const void* p) {
    uint32_t a;
    asm("{ .reg .u64 t; cvta.to.shared.u64 t, %1; cvt.u32.u64 %0, t; }" : "=r"(a) : "l"(p));
    return a;
}
// fast truncation split: hi = trunc-bf16 (byte_perm pack), lo = rounded residual
__device__ __forceinline__ void fsplit(float x0, float x1, uint32_t& hp, uint32_t& lp) {
    uint32_t u0 = __float_as_uint(x0), u1 = __float_as_uint(x1);
    hp = __byte_perm(u0, u1, 0x7632);     // [hi16(x0), hi16(x1)]
    float l0 = x0 - __uint_as_float(u0 & 0xFFFF0000u);
    float l1 = x1 - __uint_as_float(u1 & 0xFFFF0000u);
    asm("cvt.rn.bf16x2.f32 %0, %1, %2;" : "=r"(lp) : "f"(l1), "f"(l0));
}
// precise (rounded hi, exact residual) split for attr store
__device__ __forceinline__ void split1(float v, __nv_bfloat16& h, __nv_bfloat16& l) {
    h = __float2bfloat16(v);
    l = __float2bfloat16(v - __bfloat162float(h));
}
__device__ __forceinline__ void split2(float a, float b, uint32_t& hp, uint32_t& lp) {
    __nv_bfloat16 hx, hy, lx, ly;
    split1(a, hx, lx);
    split1(b, hy, ly);
    __nv_bfloat162 h2 = __halves2bfloat162(hx, hy);
    __nv_bfloat162 l2 = __halves2bfloat162(lx, ly);
    hp = *reinterpret_cast<uint32_t*>(&h2);
    lp = *reinterpret_cast<uint32_t*>(&l2);
}
__device__ __forceinline__ void mma_bf16(float* d,
                                         uint32_t a0, uint32_t a1, uint32_t a2, uint32_t a3,
                                         uint32_t b0, uint32_t b1) {
    asm volatile(
        "mma.sync.aligned.m16n8k16.row.col.f32.bf16.bf16.f32 "
        "{%0,%1,%2,%3}, {%4,%5,%6,%7}, {%8,%9}, {%0,%1,%2,%3};\n"
        : "+f"(d[0]), "+f"(d[1]), "+f"(d[2]), "+f"(d[3])
        : "r"(a0), "r"(a1), "r"(a2), "r"(a3), "r"(b0), "r"(b1));
}

// ---------------- kernel 1: per-bt CTA, 256 threads, 3 CTAs/SM ----------------
__global__ __launch_bounds__(256, 3)
void stattn_main(const float* __restrict__ x,
                 const float* __restrict__ ue_w,
                 const float* __restrict__ ue_b,
                 const float* __restrict__ be,
                 const float* __restrict__ w_w) {
    extern __shared__ __nv_bfloat16 sm[];
    __nv_bfloat16* XH = sm;                    // 64 x 136
    __nv_bfloat16* XL = sm + PLANE_BF;
    __nv_bfloat16* WH = sm + WB_OFF;           // 64 x 136
    __nv_bfloat16* WL = WH + PLANE_BF;
    float* fbase  = reinterpret_cast<float*>(sm + MISC_BF);
    float* bias_s = fbase;        // 64
    float* ww_s   = fbase + 64;   // 64
    float* e_s    = fbase + 128;  // 64
    float* a_s    = fbase + 192;  // 64

    const int tid  = threadIdx.x;
    const int lane = tid & 31;
    const int warp = tid >> 5;
    const int bt   = blockIdx.x;

    if (tid < 64) {
        e_s[tid]    = 0.0f;
        bias_s[tid] = ue_b[tid] + be[tid];
        ww_s[tid]   = w_w[tid];
    }

    const float* xg = x + (size_t)bt * (NB * DD);

    // convert x chunk kc (64 x 128 fp32) -> XH/XL
    auto convert = [&](int kc) {
#pragma unroll
        for (int it = 0; it < 8; ++it) {
            int idx = tid + it * 256;
            int n = idx >> 5, q = idx & 31;
            float4 v = __ldg(reinterpret_cast<const float4*>(xg + n * DD + kc * KCHUNK + q * 4));
            uint32_t h0, l0, h1, l1;
            fsplit(v.x, v.y, h0, l0);
            fsplit(v.z, v.w, h1, l1);
            *reinterpret_cast<uint2*>(XH + n * PCH + q * 4) = make_uint2(h0, h1);
            *reinterpret_cast<uint2*>(XL + n * PCH + q * 4) = make_uint2(l0, l1);
        }
    };
    // inline-split W chunk kc (64 x 128 fp32) -> WH/WL
    auto split_w = [&](int kc) {
#pragma unroll
        for (int it = 0; it < 8; ++it) {
            int idx = tid + it * 256;
            int j = idx >> 5, q = idx & 31;
            float4 v = __ldg(reinterpret_cast<const float4*>(ue_w + j * DD + kc * KCHUNK + q * 4));
            uint32_t h0, l0, h1, l1;
            fsplit(v.x, v.y, h0, l0);
            fsplit(v.z, v.w, h1, l1);
            *reinterpret_cast<uint2*>(WH + j * PCH + q * 4) = make_uint2(h0, h1);
            *reinterpret_cast<uint2*>(WL + j * PCH + q * 4) = make_uint2(l0, l1);
        }
    };

    split_w(0);
    convert(0);

    const int wm = warp & 3;
    const int wn = warp >> 2;
    const int r  = wm * 16 + (lane >> 2);
    const int qk = (lane & 3) * 2;

    float acc[4][4];
#pragma unroll
    for (int i = 0; i < 4; ++i)
#pragma unroll
        for (int j = 0; j < 4; ++j) acc[i][j] = 0.0f;

#pragma unroll
    for (int kc = 0; kc < 4; ++kc) {
        __syncthreads();    // chunk kc staged

#pragma unroll
        for (int kk = 0; kk < 8; ++kk) {
            const int kl = kk * 16 + qk;
            const __nv_bfloat16* pa  = XH + r * PCH + kl;
            const __nv_bfloat16* pal = XL + r * PCH + kl;
            uint32_t ah0 = ld_u32(pa);
            uint32_t ah1 = ld_u32(pa + 8 * PCH);
            uint32_t ah2 = ld_u32(pa + 8);
            uint32_t ah3 = ld_u32(pa + 8 * PCH + 8);
            uint32_t al0 = ld_u32(pal);
            uint32_t al1 = ld_u32(pal + 8 * PCH);
            uint32_t al2 = ld_u32(pal + 8);
            uint32_t al3 = ld_u32(pal + 8 * PCH + 8);
            uint32_t bh[4][2], bl[4][2];
#pragma unroll
            for (int jt = 0; jt < 4; ++jt) {
                const int jb = wn * 32 + jt * 8 + (lane >> 2);
                const __nv_bfloat16* pb  = WH + jb * PCH + kl;
                const __nv_bfloat16* pbl = WL + jb * PCH + kl;
                bh[jt][0] = ld_u32(pb);
                bh[jt][1] = ld_u32(pb + 8);
                bl[jt][0] = ld_u32(pbl);
                bl[jt][1] = ld_u32(pbl + 8);
            }
#pragma unroll
            for (int jt = 0; jt < 4; ++jt)
                mma_bf16(acc[jt], ah0, ah1, ah2, ah3, bh[jt][0], bh[jt][1]);  // hi*hi
#pragma unroll
            for (int jt = 0; jt < 4; ++jt)
                mma_bf16(acc[jt], ah0, ah1, ah2, ah3, bl[jt][0], bl[jt][1]);  // hi*lo
#pragma unroll
            for (int jt = 0; jt < 4; ++jt)
                mma_bf16(acc[jt], al0, al1, al2, al3, bh[jt][0], bh[jt][1]);  // lo*hi
        }
        __syncthreads();    // all reads of chunk kc done; buffers reusable
        if (kc < 3) {
            split_w(kc + 1);
            convert(kc + 1);
        }
    }

    // ---- epilogue: bias + leaky_relu(0.2) + dot w_w -> e[64] ----
    {
        float pe0 = 0.0f, pe1 = 0.0f;
#pragma unroll
        for (int jt = 0; jt < 4; ++jt) {
            const int j = wn * 32 + jt * 8 + qk;
            float v;
            v = acc[jt][0] + bias_s[j];     v = (v < 0.0f) ? 0.2f * v : v; pe0 = fmaf(ww_s[j],     v, pe0);
            v = acc[jt][1] + bias_s[j + 1]; v = (v < 0.0f) ? 0.2f * v : v; pe0 = fmaf(ww_s[j + 1], v, pe0);
            v = acc[jt][2] + bias_s[j];     v = (v < 0.0f) ? 0.2f * v : v; pe1 = fmaf(ww_s[j],     v, pe1);
            v = acc[jt][3] + bias_s[j + 1]; v = (v < 0.0f) ? 0.2f * v : v; pe1 = fmaf(ww_s[j + 1], v, pe1);
        }
        atomicAdd(&e_s[r], pe0);
        atomicAdd(&e_s[r + 8], pe1);
    }
    __syncthreads();

    // ---- softmax over N=64 (w_b softmax-invariant, dropped) ----
    if (warp == 0) {
        float e0 = e_s[lane], e1 = e_s[lane + 32];
        float mx = fmaxf(e0, e1);
#pragma unroll
        for (int o = 16; o; o >>= 1) mx = fmaxf(mx, __shfl_xor_sync(0xffffffffu, mx, o));
        float x0 = expf(e0 - mx), x1 = expf(e1 - mx);
        float s = x0 + x1;
#pragma unroll
        for (int o = 16; o; o >>= 1) s += __shfl_xor_sync(0xffffffffu, s, o);
        float inv = 1.0f / s;
        a_s[lane]      = x0 * inv;
        a_s[lane + 32] = x1 * inv;
    }
    __syncthreads();

    // ---- pooling: re-read exact fp32 x (L2-hot); precise attr hi/lo store ----
    {
        const int d0 = 2 * tid;
        float s0 = 0.0f, s1 = 0.0f;
#pragma unroll 8
        for (int n = 0; n < NB; ++n) {
            float2 v = __ldg(reinterpret_cast<const float2*>(xg + n * DD + d0));
            float an = a_s[n];
            s0 = fmaf(an, v.x, s0);
            s1 = fmaf(an, v.y, s1);
        }
        uint32_t hp, lp;
        split2(s0, s1, hp, lp);
        *reinterpret_cast<uint32_t*>(g_attr_h + bt * DD + d0) = hp;
        *reinterpret_cast<uint32_t*>(g_attr_l + bt * DD + d0) = lp;
    }
}

// ---------------- kernel 2: fc, 128 CTAs (32bt x 64out tiles) ----------------
__global__ __launch_bounds__(256, 2)
void stattn_fc(const float* __restrict__ fc1_w,
               const float* __restrict__ fc1_b,
               float* __restrict__ out) {
    extern __shared__ __nv_bfloat16 smb[];
    __nv_bfloat16* AH = smb;                   // 32 x 136
    __nv_bfloat16* AL = smb + FA_PLANE;
    __nv_bfloat16* WH = smb + FW_OFF;          // 64 x 136
    __nv_bfloat16* WL = WH + FW_PLANE;

    const int tid  = threadIdx.x;
    const int lane = tid & 31;
    const int warp = tid >> 5;
    const int wm   = warp & 1;      // 2 row-blocks of 16
    const int wn   = warp >> 1;     // 4 col-blocks of 16
    const int m0   = blockIdx.x * 32;   // bt tile
    const int n0   = blockIdx.y * 64;   // out-col tile

    // cp.async attr chunk kc (hi+lo): 2 planes x 32 rows x 16 granules
    auto load_a = [&](int kc) {
#pragma unroll
        for (int it = 0; it < 4; ++it) {
            int idx = tid + it * 256;
            int p = idx >> 9, rr = idx & 511;
            int j = rr >> 4, q = rr & 15;
            const __nv_bfloat16* s = (p ? g_attr_l : g_attr_h) + (m0 + j) * DD + kc * KCHUNK + q * 8;
            __nv_bfloat16* d = (p ? AL : AH) + j * PCH + q * 8;
            cp_async16(smem_u32(d), s);
        }
    };
    // inline-split fc1_w chunk kc (64 x 128 fp32)
    auto split_w = [&](int kc) {
#pragma unroll
        for (int it = 0; it < 8; ++it) {
            int idx = tid + it * 256;
            int j = idx >> 5, q = idx & 31;
            float4 v = __ldg(reinterpret_cast<const float4*>(fc1_w + (n0 + j) * DD + kc * KCHUNK + q * 4));
            uint32_t h0, l0, h1, l1;
            fsplit(v.x, v.y, h0, l0);
            fsplit(v.z, v.w, h1, l1);
            *reinterpret_cast<uint2*>(WH + j * PCH + q * 4) = make_uint2(h0, h1);
            *reinterpret_cast<uint2*>(WL + j * PCH + q * 4) = make_uint2(l0, l1);
        }
    };

    load_a(0); cp_commit();
    split_w(0);

    float acc[2][4];
#pragma unroll
    for (int i = 0; i < 2; ++i)
#pragma unroll
        for (int j = 0; j < 4; ++j) acc[i][j] = 0.0f;

    const int r  = wm * 16 + (lane >> 2);
    const int qk = (lane & 3) * 2;

#pragma unroll
    for (int kc = 0; kc < 4; ++kc) {
        cp_wait<0>();
        __syncthreads();

#pragma unroll
        for (int kk = 0; kk < 8; ++kk) {
            const int kl = kk * 16 + qk;
            const __nv_bfloat16* pa  = AH + r * PCH + kl;
            const __nv_bfloat16* pal = AL + r * PCH + kl;
            uint32_t ah0 = ld_u32(pa);
            uint32_t ah1 = ld_u32(pa + 8 * PCH);
            uint32_t ah2 = ld_u32(pa + 8);
            uint32_t ah3 = ld_u32(pa + 8 * PCH + 8);
            uint32_t al0 = ld_u32(pal);
            uint32_t al1 = ld_u32(pal + 8 * PCH);
            uint32_t al2 = ld_u32(pal + 8);
            uint32_t al3 = ld_u32(pal + 8 * PCH + 8);
            uint32_t bh[2][2], bl[2][2];
#pragma unroll
            for (int jt = 0; jt < 2; ++jt) {
                const int jb = wn * 16 + jt * 8 + (lane >> 2);
                const __nv_bfloat16* pb  = WH + jb * PCH + kl;
                const __nv_bfloat16* pbl = WL + jb * PCH + kl;
                bh[jt][0] = ld_u32(pb);
                bh[jt][1] = ld_u32(pb + 8);
                bl[jt][0] = ld_u32(pbl);
                bl[jt][1] = ld_u32(pbl + 8);
            }
#pragma unroll
            for (int jt = 0; jt < 2; ++jt)
                mma_bf16(acc[jt], ah0, ah1, ah2, ah3, bh[jt][0], bh[jt][1]);
#pragma unroll
            for (int jt = 0; jt < 2; ++jt)
                mma_bf16(acc[jt], ah0, ah1, ah2, ah3, bl[jt][0], bl[jt][1]);
#pragma unroll
            for (int jt = 0; jt < 2; ++jt)
                mma_bf16(acc[jt], al0, al1, al2, al3, bh[jt][0], bh[jt][1]);
        }
        __syncthreads();
        if (kc < 3) {
            load_a(kc + 1); cp_commit();
            split_w(kc + 1);
        }
    }

    // epilogue: out[t][b][o], bt = b*32 + t
#pragma unroll
    for (int jt = 0; jt < 2; ++jt) {
        const int j = n0 + wn * 16 + jt * 8 + qk;
        const float b0 = __ldg(fc1_b + j), b1 = __ldg(fc1_b + j + 1);
        int btr = m0 + r;
        int b = btr >> 5, t = btr & 31;
        float* o0 = out + ((size_t)t * 32 + b) * OUTC + j;
        o0[0] = acc[jt][0] + b0;
        o0[1] = acc[jt][1] + b1;
        btr = m0 + r + 8;
        b = btr >> 5; t = btr & 31;
        float* o1 = out + ((size_t)t * 32 + b) * OUTC + j;
        o1[0] = acc[jt][2] + b0;
        o1[1] = acc[jt][3] + b1;
    }
}

extern "C" void kernel_launch(void* const* d_in, const int* in_sizes, int n_in,
                              void* d_out, int out_size) {
    const float* x     = (const float*)d_in[0];  // (32,32,64,512)
    const float* ue_w  = (const float*)d_in[1];  // (64,512)
    const float* ue_b  = (const float*)d_in[2];  // (64,)
    const float* be    = (const float*)d_in[3];  // (64,)
    const float* w_w   = (const float*)d_in[4];  // (1,64)
    // d_in[5] = w_b: softmax-invariant, dropped
    const float* fc1_w = (const float*)d_in[6];  // (256,512)
    const float* fc1_b = (const float*)d_in[7];  // (256,)
    float* out = (float*)d_out;                  // [T][B][256]

    cudaFuncSetAttribute(stattn_main, cudaFuncAttributeMaxDynamicSharedMemorySize, SMEM_MAIN_BYTES);
    stattn_main<<<BT, 256, SMEM_MAIN_BYTES>>>(x, ue_w, ue_b, be, w_w);

    cudaFuncSetAttribute(stattn_fc, cudaFuncAttributeMaxDynamicSharedMemorySize, SMEMF_BYTES);
    stattn_fc<<<dim3(32, 4), 256, SMEMF_BYTES>>>(fc1_w, fc1_b, out);
}